// round 17
// baseline (speedup 1.0000x reference)
#include <cuda_runtime.h>
#include <math.h>

#define NN 8192
#define CC 128
#define TT 256
#define OUTD 128
#define RS 260   // gathered row stride: [Hn(128) | s(1) | pad(3) | HW(128)]
#define HWOFF 132
#define MAXD 144 // max row degree (Binomial(8192,0.01): mean 82, max ~116)

// ---------------- scratch (static device globals; no allocations) ----------
__device__ float g_pS[256 * CC];
__device__ float g_pQ[256 * CC];
__device__ float g_s[CC];
__device__ float g_t[CC];
__device__ float g_G[CC * CC];                  // W1 W1^T
__device__ float g_u[CC];                       // W1 b1
__device__ float g_c;                           // b1.b1
__device__ float g_P[(size_t)NN * RS];          // gathered rows, 8.5 MB
__device__ float g_Z[(size_t)NN * CC];          // Z = Hn G, own-row only, 4 MB
__device__ unsigned short g_cols16[(size_t)NN * MAXD];
__device__ int g_deg[NN];

// ---------------- BatchNorm statistics ------------------------------------
__global__ void bn_partial(const float* __restrict__ H) {
    int b = blockIdx.x, c = threadIdx.x;
    const float* p = H + (size_t)b * 32 * CC + c;
    float s = 0.f, q = 0.f;
#pragma unroll 8
    for (int r = 0; r < 32; r++) {
        float h = p[(size_t)r * CC];
        s += h; q += h * h;
    }
    g_pS[b * CC + c] = s;
    g_pQ[b * CC + c] = q;
}

__global__ void bn_final(const float* __restrict__ gamma,
                         const float* __restrict__ beta) {
    int c = threadIdx.x;
    float s = 0.f, q = 0.f;
#pragma unroll 8
    for (int b = 0; b < 256; b++) { s += g_pS[b * CC + c]; q += g_pQ[b * CC + c]; }
    float mu  = s / (float)NN;
    float var = q / (float)NN - mu * mu;           // biased variance
    float r   = rsqrtf(var + 1e-5f);
    float sc  = r * gamma[c];
    g_s[c] = sc;
    g_t[c] = beta[c] - mu * sc;
}

// ---------------- prep: G = W1 W1^T ----------------------------------------
__global__ void __launch_bounds__(256)
prep_G(const float* __restrict__ W1) {
    int idx = blockIdx.x * 256 + threadIdx.x;   // 64 blocks -> 16384 entries
    int a = idx >> 7, b = idx & 127;
    const float4* wa = (const float4*)(W1 + (size_t)a * TT);
    const float4* wb = (const float4*)(W1 + (size_t)b * TT);
    float g = 0.f;
#pragma unroll 8
    for (int t = 0; t < TT / 4; t++) {
        float4 x = wa[t], y = wb[t];
        g += x.x * y.x + x.y * y.y + x.z * y.z + x.w * y.w;
    }
    g_G[a * CC + b] = g;
}

// ---------------- prep: u = W1 b1, c = b1.b1 --------------------------------
__global__ void prep_u(const float* __restrict__ W1,
                       const float* __restrict__ b1) {
    int a = threadIdx.x;                         // <<<1,128>>>
    float u = 0.f;
    for (int t = 0; t < TT; t++) u += W1[(size_t)a * TT + t] * b1[t];
    g_u[a] = u;
    if (a == 0) {
        float c = 0.f;
        for (int t = 0; t < TT; t++) c += b1[t] * b1[t];
        g_c = c;
    }
}

// ---------------- Hn + s: write BN(H) rows and s'_i into g_P ----------------
__global__ void __launch_bounds__(256)
hn_s(const float* __restrict__ H) {
    int tid = threadIdx.x, warp = tid >> 5, lane = tid & 31;
    int row = blockIdx.x * 8 + warp;             // <<<1024,256>>>
    float4 sc4 = ((const float4*)g_s)[lane];
    float4 tt4 = ((const float4*)g_t)[lane];
    float4 h4  = ((const float4*)(H + (size_t)row * CC))[lane];
    float4 hn;
    hn.x = h4.x * sc4.x + tt4.x;
    hn.y = h4.y * sc4.y + tt4.y;
    hn.z = h4.z * sc4.z + tt4.z;
    hn.w = h4.w * sc4.w + tt4.w;
    ((float4*)(g_P + (size_t)row * RS))[lane] = hn;
    float4 u4 = ((const float4*)g_u)[lane];
    float s = hn.x * u4.x + hn.y * u4.y + hn.z * u4.z + hn.w * u4.w;
#pragma unroll
    for (int d = 16; d; d >>= 1) s += __shfl_xor_sync(0xFFFFFFFFu, s, d);
    if (lane == 0) g_P[(size_t)row * RS + 128] = s + 0.5f * g_c;
}

// ------- adjacency compaction: 1 row/CTA, 8 warps, 8-deep prefetch (R13) ---
__global__ void __launch_bounds__(256)
compact_adj(const float* __restrict__ A) {
    __shared__ int cCnt;
    int i = blockIdx.x;
    int tid = threadIdx.x, warp = tid >> 5, lane = tid & 31;

    if (tid == 0) cCnt = 0;
    const float4* rowp = (const float4*)(A + (size_t)i * NN) + warp * 256 + lane;
    float4 vbuf[8];
#pragma unroll
    for (int j = 0; j < 8; j++) vbuf[j] = rowp[j * 32];
    __syncthreads();

    unsigned short* cols = g_cols16 + (size_t)i * MAXD;
#pragma unroll
    for (int c = 0; c < 8; c++) {
        float4 v = vbuf[c];
        unsigned b0 = __ballot_sync(0xFFFFFFFFu, v.x != 0.f);
        unsigned b1 = __ballot_sync(0xFFFFFFFFu, v.y != 0.f);
        unsigned b2 = __ballot_sync(0xFFFFFFFFu, v.z != 0.f);
        unsigned b3 = __ballot_sync(0xFFFFFFFFu, v.w != 0.f);
        int total = __popc(b0) + __popc(b1) + __popc(b2) + __popc(b3);
        int base = 0;
        if (lane == 0 && total) base = atomicAdd(&cCnt, total);
        base = __shfl_sync(0xFFFFFFFFu, base, 0);
        unsigned lt = (1u << lane) - 1u;
        int col = warp * 1024 + c * 128 + lane * 4;
        int p;
        if (v.x != 0.f) { p = base + __popc(b0 & lt);
                          if (p < MAXD) cols[p] = (unsigned short)col; }
        if (v.y != 0.f) { p = base + __popc(b0) + __popc(b1 & lt);
                          if (p < MAXD) cols[p] = (unsigned short)(col + 1); }
        if (v.z != 0.f) { p = base + __popc(b0) + __popc(b1) + __popc(b2 & lt);
                          if (p < MAXD) cols[p] = (unsigned short)(col + 2); }
        if (v.w != 0.f) { p = base + __popc(b0) + __popc(b1) + __popc(b2) + __popc(b3 & lt);
                          if (p < MAXD) cols[p] = (unsigned short)(col + 3); }
    }
    __syncthreads();
    if (tid == 0) g_deg[i] = min(cCnt, MAXD);
}

// ------- projection GEMM: [Z | HW] = Hn @ [G | Wo], 128x64 tiles, N=256 ----
__global__ void __launch_bounds__(256)
gemm_proj(const float* __restrict__ H,
          const float* __restrict__ Wo,
          const float* __restrict__ bo) {
    __shared__ float As[32][132];
    __shared__ float Bs[32][68];
    int tid = threadIdx.x;
    int tx = tid & 15, ty = tid >> 4;
    int m0 = blockIdx.y * 128, n0 = blockIdx.x * 64;   // gridDim.x = 4
    float acc[8][4] = {};

    for (int k0 = 0; k0 < CC; k0 += 32) {
        {   // A tile with BN folded
            int kk = tid & 31, r0 = tid >> 5;
            float sc = g_s[k0 + kk], tt = g_t[k0 + kk];
#pragma unroll
            for (int rr = 0; rr < 128; rr += 8) {
                float h = H[(size_t)(m0 + r0 + rr) * CC + k0 + kk];
                As[kk][r0 + rr] = h * sc + tt;
            }
        }
        {   // B tile: virtual concat [G | Wo]
            int n = tid & 63, kb = tid >> 6;
#pragma unroll
            for (int kq = 0; kq < 32; kq += 4) {
                int k = k0 + kq + kb;
                int gn = n0 + n;
                float v = (gn < CC) ? g_G[k * CC + gn]
                                    : Wo[(size_t)k * OUTD + (gn - CC)];
                Bs[kq + kb][n] = v;
            }
        }
        __syncthreads();
#pragma unroll
        for (int kk = 0; kk < 32; kk++) {
            float4 a0 = *(const float4*)&As[kk][ty * 8];
            float4 a1 = *(const float4*)&As[kk][ty * 8 + 4];
            float4 b4 = *(const float4*)&Bs[kk][tx * 4];
            float a[8] = {a0.x, a0.y, a0.z, a0.w, a1.x, a1.y, a1.z, a1.w};
            float bb[4] = {b4.x, b4.y, b4.z, b4.w};
#pragma unroll
            for (int i2 = 0; i2 < 8; i2++)
#pragma unroll
                for (int j = 0; j < 4; j++) acc[i2][j] += a[i2] * bb[j];
        }
        __syncthreads();
    }
    {
        int gn = n0 + tx * 4;
        if (gn < CC) {      // Z block: no bias, to g_Z
#pragma unroll
            for (int i2 = 0; i2 < 8; i2++) {
                int row = m0 + ty * 8 + i2;
                float4 o = make_float4(acc[i2][0], acc[i2][1],
                                       acc[i2][2], acc[i2][3]);
                *(float4*)(g_Z + (size_t)row * CC + gn) = o;
            }
        } else {            // HW block: +bo, to g_P at HWOFF
            float4 bias = *(const float4*)&bo[gn - CC];
#pragma unroll
            for (int i2 = 0; i2 < 8; i2++) {
                int row = m0 + ty * 8 + i2;
                float4 o;
                o.x = acc[i2][0] + bias.x;
                o.y = acc[i2][1] + bias.y;
                o.z = acc[i2][2] + bias.z;
                o.w = acc[i2][3] + bias.w;
                *(float4*)(g_P + (size_t)row * RS + HWOFF + (gn - CC)) = o;
            }
        }
    }
}

// ---- mega-fused: factored SDDMM + softmax + half-row TMA + float4 SpMM ----
__global__ void __launch_bounds__(256, 8)
mega_row(float* __restrict__ outY, float* __restrict__ outA) {
    int i = blockIdx.x;
    __shared__ __align__(16) float sRowH[4096];   // 16 KB half-row buffer
    __shared__ __align__(16) float sZ[CC];
    __shared__ int    sCols[MAXD];
    __shared__ float2 sEdge[MAXD];                // {E, g_P index bits}
    __shared__ float  sW1[MAXD];
    __shared__ float  red[8];
    __shared__ __align__(16) float4 accS4[224];
    __shared__ float  sDiag, sInv1, sInv2, sDcoef;

    int tid = threadIdx.x, warp = tid >> 5, lane = tid & 31;
    int deg = g_deg[i];
    float sI = g_P[(size_t)i * RS + 128];         // s'_i (L2 broadcast)

    // zero half buffer; load Z row; load cols
    float4 z = make_float4(0.f, 0.f, 0.f, 0.f);
    float4* sR4 = (float4*)sRowH;
#pragma unroll
    for (int c = 0; c < 4; c++) sR4[tid + c * 256] = z;
    if (tid == 0) sDiag = 0.f;
    if (tid < CC) sZ[tid] = g_Z[(size_t)i * CC + tid];
    if (tid < deg) sCols[tid] = (int)g_cols16[(size_t)i * MAXD + tid];
    __syncthreads();

    // (1) factored SDDMM: p = Z_i . Hn_j + s_i + s_j, warp/edge, 2 in flight
    {
        const float4* sZ4 = (const float4*)sZ;
        float4 a0 = sZ4[lane];                    // loop-invariant
        for (int k = warp; k < deg; k += 16) {
            int  k2   = k + 8;
            bool has2 = k2 < deg;
            int  c0 = sCols[k];
            int  c1 = sCols[has2 ? k2 : k];
            const float* h0f = g_P + (size_t)c0 * RS;
            const float* h1f = g_P + (size_t)c1 * RS;
            float sj0 = 0.f, sj1 = 0.f;
            if (lane == 0) { sj0 = h0f[128]; sj1 = h1f[128]; }
            float4 x0 = ((const float4*)h0f)[lane];
            float4 y0 = ((const float4*)h1f)[lane];
            float p0 = a0.x * x0.x + a0.y * x0.y + a0.z * x0.z + a0.w * x0.w;
            float p1 = a0.x * y0.x + a0.y * y0.y + a0.z * y0.z + a0.w * y0.w;
#pragma unroll
            for (int d = 16; d; d >>= 1) {
                p0 += __shfl_xor_sync(0xFFFFFFFFu, p0, d);
                p1 += __shfl_xor_sync(0xFFFFFFFFu, p1, d);
            }
            if (lane == 0) {
                p0 += sI + sj0;
                p1 += sI + sj1;
                sEdge[k] = make_float2(__expf(1.f / (1.f + __expf(-p0))),
                                       __int_as_float(c0 * RS + HWOFF));
                if (has2)
                    sEdge[k2] = make_float2(__expf(1.f / (1.f + __expf(-p1))),
                                            __int_as_float(c1 * RS + HWOFF));
            }
        }
    }
    __syncthreads();

    // (2) shared softmax sums: exp(v+1)=e*exp(v) -> one sum serves both
    float E = 0.f; int col = -1;
    if (tid < deg) {
        col = sCols[tid];
        E = sEdge[tid].x;
        if (col == i) sDiag = E;
    }
    {
        float s = E;
#pragma unroll
        for (int d = 16; d; d >>= 1) s += __shfl_xor_sync(0xFFFFFFFFu, s, d);
        if (lane == 0) red[warp] = s;
    }
    __syncthreads();
    if (tid == 0) {
        float sum2 = red[0] + red[1] + red[2] + red[3]
                   + red[4] + red[5] + red[6] + red[7];
        float dc   = 1.718281828459045f * sDiag;
        sInv1  = 1.f / (sum2 + dc);
        sInv2  = 1.f / sum2;
        sDcoef = dc;
    }
    __syncthreads();
    if (tid < deg) {
        float E1 = (col == i) ? 2.718281828459045f * E : E;
        float w1 = E1 * sInv1;
        sW1[tid] = w1;
        if (col < 4096) sRowH[col] = w1;
    }
    __syncthreads();

    // (3) async bulk store of half 0 (overlaps with SpMM below)
    if (outA && tid == 0) {
        unsigned int saddr;
        asm volatile("{ .reg .u64 t; cvta.to.shared.u64 t, %1; cvt.u32.u64 %0, t; }"
                     : "=r"(saddr) : "l"(sRowH));
        asm volatile("fence.proxy.async.shared::cta;" ::: "memory");
        asm volatile("cp.async.bulk.global.shared::cta.bulk_group [%0], [%1], %2;"
                     :: "l"(outA + (size_t)i * NN), "r"(saddr), "r"(4096 * 4)
                     : "memory");
        asm volatile("cp.async.bulk.commit_group;" ::: "memory");
    }

    // (4) SpMM: 8 warp-partitions over edges, float4 per lane (4 dims)
    {
        float4 S = z;
        int k = warp;
        for (; k + 8 < deg; k += 16) {
            float2 e0 = sEdge[k], e1 = sEdge[k + 8];
            const float4* h0 = (const float4*)(g_P + __float_as_int(e0.y));
            const float4* h1 = (const float4*)(g_P + __float_as_int(e1.y));
            float4 a = h0[lane], b = h1[lane];
            S.x += e0.x * a.x; S.y += e0.x * a.y;
            S.z += e0.x * a.z; S.w += e0.x * a.w;
            S.x += e1.x * b.x; S.y += e1.x * b.y;
            S.z += e1.x * b.z; S.w += e1.x * b.w;
        }
        for (; k < deg; k += 8) {
            float2 e = sEdge[k];
            const float4* h = (const float4*)(g_P + __float_as_int(e.y));
            float4 a = h[lane];
            S.x += e.x * a.x; S.y += e.x * a.y;
            S.z += e.x * a.z; S.w += e.x * a.w;
        }
        if (warp) accS4[(warp - 1) * 32 + lane] = S;
        __syncthreads();
        if (warp == 0) {
#pragma unroll
            for (int p = 0; p < 7; p++) {
                float4 t = accS4[p * 32 + lane];
                S.x += t.x; S.y += t.y; S.z += t.z; S.w += t.w;
            }
            float4 hi = *(const float4*)(g_P + (size_t)i * RS + HWOFF + lane * 4);
            float i1 = sInv1, i2 = sInv2, dc = sDcoef;
            float a1x = i1 * (S.x + dc * hi.x), a2x = i2 * S.x;
            float a1y = i1 * (S.y + dc * hi.y), a2y = i2 * S.y;
            float a1z = i1 * (S.z + dc * hi.z), a2z = i2 * S.z;
            float a1w = i1 * (S.w + dc * hi.w), a2w = i2 * S.w;
            float4 o;
            o.x = (a1x >= 0.f ? a1x : 0.01f * a1x) + (a2x >= 0.f ? a2x : 0.01f * a2x);
            o.y = (a1y >= 0.f ? a1y : 0.01f * a1y) + (a2y >= 0.f ? a2y : 0.01f * a2y);
            o.z = (a1z >= 0.f ? a1z : 0.01f * a1z) + (a2z >= 0.f ? a2z : 0.01f * a2z);
            o.w = (a1w >= 0.f ? a1w : 0.01f * a1w) + (a2w >= 0.f ? a2w : 0.01f * a2w);
            *(float4*)(outY + (size_t)i * OUTD + lane * 4) = o;
        }
    }

    // (5) half 1: wait for TMA read of half 0, re-zero, scatter, store
    if (outA) {
        __syncthreads();
        if (tid == 0)
            asm volatile("cp.async.bulk.wait_group.read 0;" ::: "memory");
        __syncthreads();
#pragma unroll
        for (int c = 0; c < 4; c++) sR4[tid + c * 256] = z;
        __syncthreads();
        if (tid < deg) {
            int c2 = sCols[tid];
            if (c2 >= 4096) sRowH[c2 - 4096] = sW1[tid];
        }
        __syncthreads();
        if (tid == 0) {
            unsigned int saddr;
            asm volatile("{ .reg .u64 t; cvta.to.shared.u64 t, %1; cvt.u32.u64 %0, t; }"
                         : "=r"(saddr) : "l"(sRowH));
            asm volatile("fence.proxy.async.shared::cta;" ::: "memory");
            asm volatile("cp.async.bulk.global.shared::cta.bulk_group [%0], [%1], %2;"
                         :: "l"(outA + (size_t)i * NN + 4096), "r"(saddr), "r"(4096 * 4)
                         : "memory");
            asm volatile("cp.async.bulk.commit_group;" ::: "memory");
            asm volatile("cp.async.bulk.wait_group.read 0;" ::: "memory");
        }
        __syncthreads();
    }
}

// ---------------- launch ---------------------------------------------------
extern "C" void kernel_launch(void* const* d_in, const int* in_sizes, int n_in,
                              void* d_out, int out_size) {
    const float* H     = (const float*)d_in[0];
    const float* A     = (const float*)d_in[1];
    const float* gamma = (const float*)d_in[2];
    const float* beta  = (const float*)d_in[3];
    const float* W1    = (const float*)d_in[4];
    const float* b1    = (const float*)d_in[5];
    const float* Wo    = (const float*)d_in[6];
    const float* bo    = (const float*)d_in[7];

    float* outY = (float*)d_out;
    float* outA = nullptr;
    if ((long long)out_size >= (long long)NN * OUTD + (long long)NN * NN)
        outA = (float*)d_out + (size_t)NN * OUTD;

    compact_adj<<<NN, 256>>>(A);
    bn_partial<<<256, 128>>>(H);
    bn_final<<<1, 128>>>(gamma, beta);
    prep_G<<<64, 256>>>(W1);
    prep_u<<<1, 128>>>(W1, b1);
    hn_s<<<1024, 256>>>(H);
    gemm_proj<<<dim3(4, 64), 256>>>(H, Wo, bo);
    mega_row<<<NN, 256>>>(outY, outA);
}